// round 14
// baseline (speedup 1.0000x reference)
#include <cuda_runtime.h>
#include <cuda_bf16.h>
#include <math.h>
#include <stdint.h>

#define T_      3
#define RESO    24
#define DIM_    768
#define HEADS_  16
#define DH_     48
#define EMB_    1024
#define MLP_    3072
#define HW      576
#define NTOK    1728
#define FUSED_N 5376
#define QKV_N   2304
#define K2TOT   3840
#define EPS_    1e-5f
#define NSPLIT  6
#define KSPLIT2 640
#define MBLKS   112              // ceil(1792/16) padded token m-blocks
#define KB16H   48               // 768/16  k16-blocks (gemm1)
#define KB16A   240              // 3840/16 k16-blocks (gemm2)
#define SMEM_BYTES 65536         // 2 stages x 4 planes x 8KB

// ---------------- scratch (device globals, zero-initialized) -------------------
__device__ float    g_mod[T_ * 2 * DIM_];
__device__ float    g_qkv[(size_t)NTOK * QKV_N];
__device__ float    g_q[HEADS_ * NTOK * DH_];
__device__ float    g_k[HEADS_ * NTOK * DH_];
__device__ float    g_v[HEADS_ * NTOK * DH_];
__device__ float    g_part[(size_t)NSPLIT * NTOK * DIM_];
// bf16 hi/lo operand planes, fragment-major (m16n8k16 atoms, 128 words/atom)
__device__ unsigned g_hH[(size_t)MBLKS * KB16H * 128];
__device__ unsigned g_hL[(size_t)MBLKS * KB16H * 128];
__device__ unsigned g_aH[(size_t)MBLKS * KB16A * 128];
__device__ unsigned g_aL[(size_t)MBLKS * KB16A * 128];
__device__ unsigned g_w1H[(size_t)(FUSED_N / 16) * KB16H * 128];
__device__ unsigned g_w1L[(size_t)(FUSED_N / 16) * KB16H * 128];
__device__ unsigned g_w2H[(size_t)(DIM_ / 16) * KB16A * 128];
__device__ unsigned g_w2L[(size_t)(DIM_ / 16) * KB16A * 128];

__device__ __forceinline__ float silu_f(float x) { return x / (1.f + expf(-x)); }

__device__ __forceinline__ void split_bf(float v, float& hi_f, float& lo_f) {
    __nv_bfloat16 h = __float2bfloat16(v);
    hi_f = __bfloat162float(h);
    lo_f = v - hi_f;
}
__device__ __forceinline__ unsigned pack_bf2(float x, float y) {
    __nv_bfloat162 h = __floats2bfloat162_rn(x, y);   // low = x
    return *(unsigned*)&h;
}
__device__ __forceinline__ void cpa16(unsigned dst, const void* src) {
    asm volatile("cp.async.cg.shared.global [%0], [%1], 16;" :: "r"(dst), "l"(src));
}
#define CP_COMMIT() asm volatile("cp.async.commit_group;" ::: "memory")
#define CP_WAIT0()  asm volatile("cp.async.wait_group 0;" ::: "memory")

// m16n8k16 fragment-major word index (32-bit words, each = bf16 pair k,k+1)
// A atom: lane=(m&7)*4+((k>>1)&3), j=((k>>3)&1)*2+((m>>3)&1), half=k&1
__device__ __forceinline__ size_t aposW(int m, int k, int KB16) {
    return ((size_t)(m >> 4) * KB16 + (k >> 4)) * 128 +
           (size_t)((((m & 7) * 4 + ((k >> 1) & 3)) * 4) + ((k >> 3) & 1) * 2 + ((m >> 3) & 1));
}

__device__ __forceinline__ void mmab(float* d, uint4 a, uint32_t b0, uint32_t b1) {
    asm volatile(
        "mma.sync.aligned.m16n8k16.row.col.f32.bf16.bf16.f32 "
        "{%0,%1,%2,%3}, {%4,%5,%6,%7}, {%8,%9}, {%0,%1,%2,%3};"
        : "+f"(d[0]), "+f"(d[1]), "+f"(d[2]), "+f"(d[3])
        : "r"(a.x), "r"(a.y), "r"(a.z), "r"(a.w), "r"(b0), "r"(b1));
}

// copy one plane tile: 8 blocks x 2 k16-atoms = 16 atoms x 512B = 8KB
__device__ __forceinline__ void load_plane(uint4* dst, const unsigned* src,
                                           int blk0, int KB16, int kat0, int tid) {
#pragma unroll
    for (int p = 0; p < 2; p++) {
        int lin = p * 256 + tid;
        int atom = lin >> 5, l16 = lin & 31;
        const unsigned* s = src +
            ((size_t)(blk0 + (atom >> 1)) * KB16 + kat0 + (atom & 1)) * 128 + l16 * 4;
        cpa16((unsigned)__cvta_generic_to_shared(dst + atom * 32 + l16), s);
    }
}

// ---------------- kernel: weights -> hi/lo fragment-major planes ---------------
__global__ void __launch_bounds__(256) k_tr(const float* __restrict__ src,
                                            unsigned* __restrict__ dstH,
                                            unsigned* __restrict__ dstL,
                                            int N, int KB16, int koff) {
    __shared__ float ts[32][33];
    int k0 = blockIdx.y * 32, n0 = blockIdx.x * 32;
    int lx = threadIdx.x & 31, ly = threadIdx.x >> 5;
#pragma unroll
    for (int r = 0; r < 4; r++)
        ts[ly + r * 8][lx] = src[(size_t)(k0 + ly + r * 8) * N + n0 + lx];
    __syncthreads();
    // 8 warps: plane = w>>2 (0 hi, 1 lo), natom = w&1, katom = (w>>1)&1
    int w = threadIdx.x >> 5, lane = threadIdx.x & 31;
    int plane = w >> 2, natom = w & 1, katom = (w >> 1) & 1;
    int g = lane >> 2, tig = lane & 3;
    unsigned* dst = plane ? dstL : dstH;
    size_t atomIdx = ((size_t)((n0 >> 4) + natom) * KB16 + ((koff + k0) >> 4) + katom) * 128;
#pragma unroll
    for (int j = 0; j < 4; j++) {
        int p = j >> 1, kh = j & 1;
        int n_l = natom * 16 + p * 8 + g;
        int k_l = katom * 16 + kh * 8 + 2 * tig;
        float h0, l0, h1, l1;
        split_bf(ts[k_l][n_l], h0, l0);
        split_bf(ts[k_l + 1][n_l], h1, l1);
        dst[atomIdx + lane * 4 + j] = plane ? pack_bf2(l0, l1) : pack_bf2(h0, h1);
    }
}

// ---------------- kernel 1: mod = silu(emb) @ w_mod + b_mod -------------------
__global__ void k_mod(const float* __restrict__ emb,
                      const float* __restrict__ w_mod,
                      const float* __restrict__ b_mod) {
    __shared__ float se[EMB_];
    int t = blockIdx.y;
    for (int i = threadIdx.x; i < EMB_; i += 256)
        se[i] = silu_f(emb[t * EMB_ + i]);
    __syncthreads();
    int j = blockIdx.x * 256 + threadIdx.x;
    float acc = b_mod[j];
#pragma unroll 4
    for (int e = 0; e < EMB_; e++)
        acc += se[e] * w_mod[e * (2 * DIM_) + j];
    g_mod[t * (2 * DIM_) + j] = acc;
}

// ---------------- kernel 2: LN -> hi/lo planes --------------------------------
__global__ void k_ln(const float* __restrict__ x) {
    int n = blockIdx.x;
    int t = n / HW, hw = n % HW;
    const float* xp = x + (size_t)t * DIM_ * HW + hw;
    int c0 = threadIdx.x, c1 = c0 + 256, c2 = c0 + 512;
    float v0 = xp[(size_t)c0 * HW];
    float v1 = xp[(size_t)c1 * HW];
    float v2 = xp[(size_t)c2 * HW];
    float s  = v0 + v1 + v2;
    float sq = v0 * v0 + v1 * v1 + v2 * v2;
    __shared__ float rs[8], rq[8];
#pragma unroll
    for (int o = 16; o; o >>= 1) {
        s  += __shfl_xor_sync(~0u, s, o);
        sq += __shfl_xor_sync(~0u, sq, o);
    }
    int wid = threadIdx.x >> 5, lid = threadIdx.x & 31;
    if (lid == 0) { rs[wid] = s; rq[wid] = sq; }
    __syncthreads();
    if (threadIdx.x == 0) {
        float ts = 0.f, tq = 0.f;
        for (int i = 0; i < 8; i++) { ts += rs[i]; tq += rq[i]; }
        rs[0] = ts; rq[0] = tq;
    }
    __syncthreads();
    float mean = rs[0] * (1.f / DIM_);
    float var  = rq[0] * (1.f / DIM_) - mean * mean;
    float inv  = rsqrtf(var + EPS_);
    const float* md = g_mod + t * (2 * DIM_);
    __nv_bfloat16* hH = (__nv_bfloat16*)g_hH;
    __nv_bfloat16* hL = (__nv_bfloat16*)g_hL;
#pragma unroll
    for (int r = 0; r < 3; r++) {
        int c = c0 + r * 256;
        float v = (r == 0) ? v0 : (r == 1) ? v1 : v2;
        float y = (v - mean) * inv * (1.f + md[c]) + md[DIM_ + c];
        float hi, lo;
        split_bf(y, hi, lo);
        size_t wI = aposW(n, c, KB16H) * 2 + (c & 1);
        hH[wI] = __float2bfloat16(hi);
        hL[wI] = __float2bfloat16(lo);
    }
}

// ---------------- GEMM 1: fused = h @ W_fused + b_fused (bf16 hi/lo) ----------
// CTA 128x128, 8 warps (4m x 2n), k-chunk 32 (2 k16 slices), 2-stage cp.async.
__global__ void __launch_bounds__(256, 2) k_gemm1_mma(const float* __restrict__ bf) {
    extern __shared__ uint4 smU[];   // [2][AH 512 | AL 512 | BH 512 | BL 512]
    const int tid = threadIdx.x, wid = tid >> 5, lane = tid & 31;
    const int wm = wid & 3, wn = wid >> 2;
    const int g = lane >> 2, tig = lane & 3;
    const int bm = blockIdx.y * 128, BN = blockIdx.x * 128;
    const int mblk0 = bm >> 4, nblk0 = BN >> 4;

    float acc[2][8][4];
#pragma unroll
    for (int a = 0; a < 2; a++)
#pragma unroll
        for (int b = 0; b < 8; b++)
#pragma unroll
            for (int c = 0; c < 4; c++) acc[a][b][c] = 0.f;

    load_plane(smU,        g_hH,  mblk0, KB16H, 0, tid);
    load_plane(smU + 512,  g_hL,  mblk0, KB16H, 0, tid);
    load_plane(smU + 1024, g_w1H, nblk0, KB16H, 0, tid);
    load_plane(smU + 1536, g_w1L, nblk0, KB16H, 0, tid);
    CP_COMMIT(); CP_WAIT0();
    __syncthreads();

    const int NIT = KB16H / 2;   // 24
    for (int kt = 0; kt < NIT; kt++) {
        int cur = kt & 1, nxt = cur ^ 1;
        if (kt + 1 < NIT) {
            int kat = (kt + 1) * 2;
            load_plane(smU + nxt * 2048,        g_hH,  mblk0, KB16H, kat, tid);
            load_plane(smU + nxt * 2048 + 512,  g_hL,  mblk0, KB16H, kat, tid);
            load_plane(smU + nxt * 2048 + 1024, g_w1H, nblk0, KB16H, kat, tid);
            load_plane(smU + nxt * 2048 + 1536, g_w1L, nblk0, KB16H, kat, tid);
            CP_COMMIT();
        }
        const uint4* AH = smU + cur * 2048;
        const uint4* AL = AH + 512;
        const uint4* BH = AH + 1024;
        const uint4* BL = AH + 1536;
#pragma unroll
        for (int ks = 0; ks < 2; ks++) {
            uint4 ah0 = AH[((wm * 2 + 0) * 2 + ks) * 32 + lane];
            uint4 ah1 = AH[((wm * 2 + 1) * 2 + ks) * 32 + lane];
            uint4 al0 = AL[((wm * 2 + 0) * 2 + ks) * 32 + lane];
            uint4 al1 = AL[((wm * 2 + 1) * 2 + ks) * 32 + lane];
#pragma unroll
            for (int nbp = 0; nbp < 4; nbp++) {
                uint4 bh = BH[((wn * 4 + nbp) * 2 + ks) * 32 + lane];
                uint4 bl = BL[((wn * 4 + nbp) * 2 + ks) * 32 + lane];
                mmab(acc[0][nbp * 2 + 0], ah0, bh.x, bh.y);
                mmab(acc[0][nbp * 2 + 1], ah0, bh.z, bh.w);
                mmab(acc[1][nbp * 2 + 0], ah1, bh.x, bh.y);
                mmab(acc[1][nbp * 2 + 1], ah1, bh.z, bh.w);
                mmab(acc[0][nbp * 2 + 0], ah0, bl.x, bl.y);
                mmab(acc[0][nbp * 2 + 1], ah0, bl.z, bl.w);
                mmab(acc[1][nbp * 2 + 0], ah1, bl.x, bl.y);
                mmab(acc[1][nbp * 2 + 1], ah1, bl.z, bl.w);
                mmab(acc[0][nbp * 2 + 0], al0, bh.x, bh.y);
                mmab(acc[0][nbp * 2 + 1], al0, bh.z, bh.w);
                mmab(acc[1][nbp * 2 + 0], al1, bh.x, bh.y);
                mmab(acc[1][nbp * 2 + 1], al1, bh.z, bh.w);
            }
        }
        if (kt + 1 < NIT) CP_WAIT0();
        __syncthreads();
    }

    const bool qkv_tile = (BN < QKV_N);
#pragma unroll
    for (int mb = 0; mb < 2; mb++) {
#pragma unroll
        for (int rr = 0; rr < 2; rr++) {
            int row = bm + wm * 32 + mb * 16 + rr * 8 + g;
            if (row >= NTOK) continue;
#pragma unroll
            for (int nb = 0; nb < 8; nb++) {
                int col = BN + wn * 64 + nb * 8 + 2 * tig;
                float vx = acc[mb][nb][rr * 2 + 0] + bf[col];
                float vy = acc[mb][nb][rr * 2 + 1] + bf[col + 1];
                if (qkv_tile) {
                    *(float2*)(g_qkv + (size_t)row * QKV_N + col) = make_float2(vx, vy);
                } else {
                    float sx = silu_f(vx), sy = silu_f(vy);
                    float hx, lx_, hy, ly_;
                    split_bf(sx, hx, lx_);
                    split_bf(sy, hy, ly_);
                    size_t wI = aposW(row, col - 1536, KB16A);
                    g_aH[wI] = pack_bf2(hx, hy);
                    g_aL[wI] = pack_bf2(lx_, ly_);
                }
            }
        }
    }
}

// ---------------- GEMM 2: [xa | silu(mlp)] @ [Wo;Wm], split-K=6 (bf16) --------
__global__ void __launch_bounds__(256, 2) k_gemm2_mma() {
    extern __shared__ uint4 smU[];
    const int tid = threadIdx.x, wid = tid >> 5, lane = tid & 31;
    const int wm = wid & 3, wn = wid >> 2;
    const int g = lane >> 2, tig = lane & 3;
    const int bm = blockIdx.y * 128, BN = blockIdx.x * 128;
    const int z = blockIdx.z;
    const int mblk0 = bm >> 4, nblk0 = BN >> 4;
    const int kat0 = z * (KSPLIT2 / 16);    // 40 per split

    float acc[2][8][4];
#pragma unroll
    for (int a = 0; a < 2; a++)
#pragma unroll
        for (int b = 0; b < 8; b++)
#pragma unroll
            for (int c = 0; c < 4; c++) acc[a][b][c] = 0.f;

    load_plane(smU,        g_aH,  mblk0, KB16A, kat0, tid);
    load_plane(smU + 512,  g_aL,  mblk0, KB16A, kat0, tid);
    load_plane(smU + 1024, g_w2H, nblk0, KB16A, kat0, tid);
    load_plane(smU + 1536, g_w2L, nblk0, KB16A, kat0, tid);
    CP_COMMIT(); CP_WAIT0();
    __syncthreads();

    const int NIT = KSPLIT2 / 32;   // 20
    for (int kt = 0; kt < NIT; kt++) {
        int cur = kt & 1, nxt = cur ^ 1;
        if (kt + 1 < NIT) {
            int kat = kat0 + (kt + 1) * 2;
            load_plane(smU + nxt * 2048,        g_aH,  mblk0, KB16A, kat, tid);
            load_plane(smU + nxt * 2048 + 512,  g_aL,  mblk0, KB16A, kat, tid);
            load_plane(smU + nxt * 2048 + 1024, g_w2H, nblk0, KB16A, kat, tid);
            load_plane(smU + nxt * 2048 + 1536, g_w2L, nblk0, KB16A, kat, tid);
            CP_COMMIT();
        }
        const uint4* AH = smU + cur * 2048;
        const uint4* AL = AH + 512;
        const uint4* BH = AH + 1024;
        const uint4* BL = AH + 1536;
#pragma unroll
        for (int ks = 0; ks < 2; ks++) {
            uint4 ah0 = AH[((wm * 2 + 0) * 2 + ks) * 32 + lane];
            uint4 ah1 = AH[((wm * 2 + 1) * 2 + ks) * 32 + lane];
            uint4 al0 = AL[((wm * 2 + 0) * 2 + ks) * 32 + lane];
            uint4 al1 = AL[((wm * 2 + 1) * 2 + ks) * 32 + lane];
#pragma unroll
            for (int nbp = 0; nbp < 4; nbp++) {
                uint4 bh = BH[((wn * 4 + nbp) * 2 + ks) * 32 + lane];
                uint4 bl = BL[((wn * 4 + nbp) * 2 + ks) * 32 + lane];
                mmab(acc[0][nbp * 2 + 0], ah0, bh.x, bh.y);
                mmab(acc[0][nbp * 2 + 1], ah0, bh.z, bh.w);
                mmab(acc[1][nbp * 2 + 0], ah1, bh.x, bh.y);
                mmab(acc[1][nbp * 2 + 1], ah1, bh.z, bh.w);
                mmab(acc[0][nbp * 2 + 0], ah0, bl.x, bl.y);
                mmab(acc[0][nbp * 2 + 1], ah0, bl.z, bl.w);
                mmab(acc[1][nbp * 2 + 0], ah1, bl.x, bl.y);
                mmab(acc[1][nbp * 2 + 1], ah1, bl.z, bl.w);
                mmab(acc[0][nbp * 2 + 0], al0, bh.x, bh.y);
                mmab(acc[0][nbp * 2 + 1], al0, bh.z, bh.w);
                mmab(acc[1][nbp * 2 + 0], al1, bh.x, bh.y);
                mmab(acc[1][nbp * 2 + 1], al1, bh.z, bh.w);
            }
        }
        if (kt + 1 < NIT) CP_WAIT0();
        __syncthreads();
    }

#pragma unroll
    for (int mb = 0; mb < 2; mb++) {
#pragma unroll
        for (int rr = 0; rr < 2; rr++) {
            int row = bm + wm * 32 + mb * 16 + rr * 8 + g;
            if (row >= NTOK) continue;
            float* dst = g_part + ((size_t)z * NTOK + row) * DIM_ + BN + wn * 64;
#pragma unroll
            for (int nb = 0; nb < 8; nb++) {
                int col = nb * 8 + 2 * tig;
                *(float2*)(dst + col) =
                    make_float2(acc[mb][nb][rr * 2 + 0], acc[mb][nb][rr * 2 + 1]);
            }
        }
    }
}

// ---------------- kernel 4: qk-norm + RoPE + scatter q/k/v --------------------
__global__ void __launch_bounds__(512) k_qkv(const float* __restrict__ qn_w,
                                             const float* __restrict__ qn_b,
                                             const float* __restrict__ kn_w,
                                             const float* __restrict__ kn_b) {
    int n = blockIdx.x;
    int head = threadIdx.x >> 5;
    int lane = threadIdx.x & 31;
    int t = n / HW, hh = (n % HW) / RESO, ww = n % RESO;
    const float* fp = g_qkv + (size_t)n * QKV_N + head * DH_;
    float2 q2 = make_float2(0.f, 0.f), k2 = q2, v2 = q2;
    if (lane < 24) {
        q2 = *(const float2*)(fp + 2 * lane);
        k2 = *(const float2*)(fp + DIM_ + 2 * lane);
        v2 = *(const float2*)(fp + 2 * DIM_ + 2 * lane);
    }
    float qs = q2.x + q2.y, qq = q2.x * q2.x + q2.y * q2.y;
    float ks = k2.x + k2.y, kq = k2.x * k2.x + k2.y * k2.y;
#pragma unroll
    for (int o = 16; o; o >>= 1) {
        qs += __shfl_xor_sync(~0u, qs, o);
        qq += __shfl_xor_sync(~0u, qq, o);
        ks += __shfl_xor_sync(~0u, ks, o);
        kq += __shfl_xor_sync(~0u, kq, o);
    }
    if (lane < 24) {
        float qm = qs * (1.f / DH_), qv = qq * (1.f / DH_) - qm * qm;
        float km = ks * (1.f / DH_), kv = kq * (1.f / DH_) - km * km;
        float qi = rsqrtf(qv + EPS_), ki = rsqrtf(kv + EPS_);
        int j0 = 2 * lane, j1 = j0 + 1;
        float qn0 = (q2.x - qm) * qi * qn_w[j0] + qn_b[j0];
        float qn1 = (q2.y - qm) * qi * qn_w[j1] + qn_b[j1];
        float kn0 = (k2.x - km) * ki * kn_w[j0] + kn_b[j0];
        float kn1 = (k2.y - km) * ki * kn_w[j1] + kn_b[j1];
        int i = lane;
        int idx;  float pos;
        if (i < 8)       { idx = i;      pos = (float)t;  }
        else if (i < 16) { idx = i - 8;  pos = (float)hh; }
        else             { idx = i - 16; pos = (float)ww; }
        float ang = pos * powf(10000.f, -(float)idx * 0.125f);
        float c = cosf(ang), sn = sinf(ang);
        const float qsc = 0.14433756729740643f;  // 48^-0.5
        size_t base = ((size_t)head * NTOK + n) * DH_;
        *(float2*)(g_q + base + j0) =
            make_float2((qn0 * c - qn1 * sn) * qsc, (qn0 * sn + qn1 * c) * qsc);
        *(float2*)(g_k + base + j0) =
            make_float2(kn0 * c - kn1 * sn, kn0 * sn + kn1 * c);
        *(float2*)(g_v + base + j0) = v2;
    }
}

// ---------------- kernel 5: neighborhood attention (75 nbrs) ------------------
__global__ void __launch_bounds__(512) k_attn() {
    __shared__ float sq[HEADS_][DH_];
    int n = blockIdx.x;
    int head = threadIdx.x >> 5, lane = threadIdx.x & 31;
    int hh = (n % HW) / RESO, ww = n % RESO;
    size_t hb = (size_t)head * NTOK * DH_;
    if (lane < 24)
        *(float2*)&sq[head][2 * lane] = *(const float2*)(g_q + hb + (size_t)n * DH_ + 2 * lane);
    __syncwarp();
    int ih0 = min(max(hh - 2, 0), RESO - 5);
    int iw0 = min(max(ww - 2, 0), RESO - 5);
    float logit[3]; int nn[3];
#pragma unroll
    for (int s = 0; s < 3; s++) {
        int a = s * 32 + lane;
        logit[s] = -1e30f; nn[s] = 0;
        if (a < 75) {
            int at = a / 25, r = a % 25, ah = r / 5, aw = r % 5;
            int np = at * HW + (ih0 + ah) * RESO + (iw0 + aw);
            nn[s] = np;
            const float* kp = g_k + hb + (size_t)np * DH_;
            float d = 0.f;
#pragma unroll
            for (int j4 = 0; j4 < 12; j4++) {
                float4 kvv = *(const float4*)(kp + j4 * 4);
                d += kvv.x * sq[head][j4 * 4 + 0] + kvv.y * sq[head][j4 * 4 + 1]
                   + kvv.z * sq[head][j4 * 4 + 2] + kvv.w * sq[head][j4 * 4 + 3];
            }
            logit[s] = d;
        }
    }
    float m = fmaxf(fmaxf(logit[0], logit[1]), logit[2]);
#pragma unroll
    for (int o = 16; o; o >>= 1) m = fmaxf(m, __shfl_xor_sync(~0u, m, o));
    float p[3];
    p[0] = expf(logit[0] - m);
    p[1] = expf(logit[1] - m);
    p[2] = expf(logit[2] - m);
    float ssum = p[0] + p[1] + p[2];
#pragma unroll
    for (int o = 16; o; o >>= 1) ssum += __shfl_xor_sync(~0u, ssum, o);
    float inv = 1.f / ssum;
    float o0 = 0.f, o1 = 0.f;
#pragma unroll
    for (int s = 0; s < 3; s++) {
        int lim = (s == 2) ? 11 : 32;
        for (int src = 0; src < lim; src++) {
            float pa = __shfl_sync(~0u, p[s], src);
            int  np = __shfl_sync(~0u, nn[s], src);
            const float* vp = g_v + hb + (size_t)np * DH_;
            o0 += pa * vp[lane];
            if (lane < 16) o1 += pa * vp[lane + 32];
        }
    }
    // write xa hi/lo into gemm2 A planes (k index = channel)
    int ch = head * DH_;
    __nv_bfloat16* aH = (__nv_bfloat16*)g_aH;
    __nv_bfloat16* aL = (__nv_bfloat16*)g_aL;
    {
        int k = ch + lane;
        float hi, lo;
        split_bf(o0 * inv, hi, lo);
        size_t wI = aposW(n, k, KB16A) * 2 + (k & 1);
        aH[wI] = __float2bfloat16(hi);
        aL[wI] = __float2bfloat16(lo);
    }
    if (lane < 16) {
        int k = ch + 32 + lane;
        float hi, lo;
        split_bf(o1 * inv, hi, lo);
        size_t wI = aposW(n, k, KB16A) * 2 + (k & 1);
        aH[wI] = __float2bfloat16(hi);
        aL[wI] = __float2bfloat16(lo);
    }
}

// ---------------- kernel 7: reduce partials + skip + bias + transpose ---------
__global__ void __launch_bounds__(256) k_fin(const float* __restrict__ x,
                                             const float* __restrict__ bm_,
                                             float* __restrict__ out) {
    __shared__ float s[32][33];
    int hw0 = blockIdx.x * 32, c0 = blockIdx.y * 32, t = blockIdx.z;
    int lx = threadIdx.x & 31, lyb = threadIdx.x >> 5;
#pragma unroll
    for (int r = 0; r < 4; r++) {
        int hwl = lyb + r * 8;
        int c = c0 + lx;
        size_t nidx = ((size_t)(t * HW + hw0 + hwl)) * DIM_ + c;
        float sum = bm_[c];
#pragma unroll
        for (int z = 0; z < NSPLIT; z++)
            sum += g_part[(size_t)z * NTOK * DIM_ + nidx];
        s[hwl][lx] = sum;
    }
    __syncthreads();
#pragma unroll
    for (int r = 0; r < 4; r++) {
        int cl = lyb + r * 8;
        size_t oi = ((size_t)(t * DIM_ + c0 + cl)) * HW + hw0 + lx;
        out[oi] = x[oi] + s[lx][cl];
    }
}

// ---------------------------------- launcher ----------------------------------
extern "C" void kernel_launch(void* const* d_in, const int* in_sizes, int n_in,
                              void* d_out, int out_size) {
    const float* x       = (const float*)d_in[0];
    const float* emb     = (const float*)d_in[1];
    const float* w_mod   = (const float*)d_in[2];
    const float* b_mod   = (const float*)d_in[3];
    const float* qn_w    = (const float*)d_in[4];
    const float* qn_b    = (const float*)d_in[5];
    const float* kn_w    = (const float*)d_in[6];
    const float* kn_b    = (const float*)d_in[7];
    const float* W_fused = (const float*)d_in[8];
    const float* b_fused = (const float*)d_in[9];
    const float* W_out   = (const float*)d_in[10];
    const float* W_mlp   = (const float*)d_in[11];
    const float* b_mlp   = (const float*)d_in[12];
    float* out = (float*)d_out;

    static int attr_done = 0;
    if (!attr_done) {
        cudaFuncSetAttribute(k_gemm1_mma, cudaFuncAttributeMaxDynamicSharedMemorySize, SMEM_BYTES);
        cudaFuncSetAttribute(k_gemm2_mma, cudaFuncAttributeMaxDynamicSharedMemorySize, SMEM_BYTES);
        attr_done = 1;
    }

    unsigned *w1H, *w1L, *w2H, *w2L;
    cudaGetSymbolAddress((void**)&w1H, g_w1H);
    cudaGetSymbolAddress((void**)&w1L, g_w1L);
    cudaGetSymbolAddress((void**)&w2H, g_w2H);
    cudaGetSymbolAddress((void**)&w2L, g_w2L);

    k_mod<<<dim3(6, 3), 256>>>(emb, w_mod, b_mod);
    k_ln<<<NTOK, 256>>>(x);
    k_tr<<<dim3(FUSED_N / 32, DIM_ / 32), 256>>>(W_fused, w1H, w1L, FUSED_N, KB16H, 0);
    k_tr<<<dim3(DIM_ / 32, DIM_ / 32), 256>>>(W_out, w2H, w2L, DIM_, KB16A, 0);
    k_tr<<<dim3(DIM_ / 32, MLP_ / 32), 256>>>(W_mlp, w2H, w2L, DIM_, KB16A, DIM_);

    k_gemm1_mma<<<dim3(FUSED_N / 128, 14), 256, SMEM_BYTES>>>(b_fused);
    k_qkv<<<NTOK, 512>>>(qn_w, qn_b, kn_w, kn_b);
    k_attn<<<NTOK, 512>>>();
    k_gemm2_mma<<<dim3(DIM_ / 128, 14, NSPLIT), 256, SMEM_BYTES>>>();
    k_fin<<<dim3(RESO * RESO / 32, DIM_ / 32, T_), 256>>>(x, b_mlp, out);
}

// round 17
// speedup vs baseline: 1.2473x; 1.2473x over previous
#include <cuda_runtime.h>
#include <cuda_fp16.h>
#include <math.h>
#include <stdint.h>

#define T_      3
#define RESO    24
#define DIM_    768
#define HEADS_  16
#define DH_     48
#define EMB_    1024
#define MLP_    3072
#define HW      576
#define NTOK    1728
#define FUSED_N 5376
#define QKV_N   2304
#define K2TOT   3840
#define EPS_    1e-5f
#define NSPLIT  6
#define KSPLIT2 640
#define MBLKS   112              // ceil(1792/16) padded token m-blocks
#define KB16H   48               // 768/16  k16-atoms (gemm1)
#define KB16A   240              // 3840/16 k16-atoms (gemm2)
#define SMEM_BYTES 32768         // 2 stages x (A 8KB + B 8KB)

// ---------------- scratch (device globals, zero-initialized) -------------------
__device__ float    g_mod[T_ * 2 * DIM_];
__device__ float    g_qkv[(size_t)NTOK * QKV_N];
__device__ float    g_q[HEADS_ * NTOK * DH_];
__device__ float    g_k[HEADS_ * NTOK * DH_];
__device__ float    g_v[HEADS_ * NTOK * DH_];
__device__ float    g_part[(size_t)NSPLIT * NTOK * DIM_];
// fp16 operand planes, fragment-major (m16n8k16 atoms = 128 x 32-bit words)
__device__ unsigned g_hP[(size_t)MBLKS * KB16H * 128];
__device__ unsigned g_aP[(size_t)MBLKS * KB16A * 128];
__device__ unsigned g_w1[(size_t)(FUSED_N / 16) * KB16H * 128];
__device__ unsigned g_w2[(size_t)(DIM_ / 16) * KB16A * 128];

__device__ __forceinline__ float silu_f(float x) { return x / (1.f + expf(-x)); }
__device__ __forceinline__ unsigned pack_h2(float x, float y) {
    __half2 h = __floats2half2_rn(x, y);   // .x = low
    return *(unsigned*)&h;
}
__device__ __forceinline__ void cpa16(unsigned dst, const void* src) {
    asm volatile("cp.async.cg.shared.global [%0], [%1], 16;" :: "r"(dst), "l"(src));
}
#define CP_COMMIT() asm volatile("cp.async.commit_group;" ::: "memory")
#define CP_WAIT0()  asm volatile("cp.async.wait_group 0;" ::: "memory")

// m16n8k16 A-fragment word index (word = fp16 pair k,k+1)
// lane=(m&7)*4+((k>>1)&3), j=((k>>3)&1)*2+((m>>3)&1)
__device__ __forceinline__ size_t aposW(int m, int k, int KB16) {
    return ((size_t)(m >> 4) * KB16 + (k >> 4)) * 128 +
           (size_t)((((m & 7) * 4 + ((k >> 1) & 3)) * 4) + ((k >> 3) & 1) * 2 + ((m >> 3) & 1));
}

__device__ __forceinline__ void mmah(float* d, uint4 a, uint32_t b0, uint32_t b1) {
    asm volatile(
        "mma.sync.aligned.m16n8k16.row.col.f32.f16.f16.f32 "
        "{%0,%1,%2,%3}, {%4,%5,%6,%7}, {%8,%9}, {%0,%1,%2,%3};"
        : "+f"(d[0]), "+f"(d[1]), "+f"(d[2]), "+f"(d[3])
        : "r"(a.x), "r"(a.y), "r"(a.z), "r"(a.w), "r"(b0), "r"(b1));
}

// copy one plane tile: 8 blocks x 2 k16-atoms = 16 atoms x 512B = 8KB
__device__ __forceinline__ void load_plane(uint4* dst, const unsigned* src,
                                           int blk0, int KB16, int kat0, int tid) {
#pragma unroll
    for (int p = 0; p < 2; p++) {
        int lin = p * 256 + tid;
        int atom = lin >> 5, l16 = lin & 31;
        const unsigned* s = src +
            ((size_t)(blk0 + (atom >> 1)) * KB16 + kat0 + (atom & 1)) * 128 + l16 * 4;
        cpa16((unsigned)__cvta_generic_to_shared(dst + atom * 32 + l16), s);
    }
}

// ---------------- kernel: weights -> fp16 fragment-major -----------------------
// src [K][N] row-major; 32x32 region = 2 natoms x 2 katoms = 4 atoms.
__global__ void __launch_bounds__(256) k_tr(const float* __restrict__ src,
                                            unsigned* __restrict__ dst,
                                            int N, int KB16, int koff) {
    __shared__ float ts[32][33];
    int k0 = blockIdx.y * 32, n0 = blockIdx.x * 32;
    int lx = threadIdx.x & 31, ly = threadIdx.x >> 5;
#pragma unroll
    for (int r = 0; r < 4; r++)
        ts[ly + r * 8][lx] = src[(size_t)(k0 + ly + r * 8) * N + n0 + lx];
    __syncthreads();
    // 8 warps: atom = w&3 (natom = w&1, katom = (w>>1)&1), j-half = w>>2
    int w = threadIdx.x >> 5, lane = threadIdx.x & 31;
    int natom = w & 1, katom = (w >> 1) & 1, jh = w >> 2;
    int g = lane >> 2, tig = lane & 3;
    size_t atomIdx = ((size_t)((n0 >> 4) + natom) * KB16 + ((koff + k0) >> 4) + katom) * 128;
#pragma unroll
    for (int jj = 0; jj < 2; jj++) {
        int j = jh * 2 + jj;
        int p = j >> 1, kh = j & 1;               // B layout: j = p*2 + kh
        int n_l = natom * 16 + p * 8 + g;
        int k_l = katom * 16 + kh * 8 + 2 * tig;
        dst[atomIdx + lane * 4 + j] = pack_h2(ts[k_l][n_l], ts[k_l + 1][n_l]);
    }
}

// ---------------- kernel 1: mod = silu(emb) @ w_mod + b_mod -------------------
__global__ void k_mod(const float* __restrict__ emb,
                      const float* __restrict__ w_mod,
                      const float* __restrict__ b_mod) {
    __shared__ float se[EMB_];
    int t = blockIdx.y;
    for (int i = threadIdx.x; i < EMB_; i += 256)
        se[i] = silu_f(emb[t * EMB_ + i]);
    __syncthreads();
    int j = blockIdx.x * 256 + threadIdx.x;
    float acc = b_mod[j];
#pragma unroll 4
    for (int e = 0; e < EMB_; e++)
        acc += se[e] * w_mod[e * (2 * DIM_) + j];
    g_mod[t * (2 * DIM_) + j] = acc;
}

// ---------------- kernel 2: LN -> fp16 plane ----------------------------------
__global__ void k_ln(const float* __restrict__ x) {
    int n = blockIdx.x;
    int t = n / HW, hw = n % HW;
    const float* xp = x + (size_t)t * DIM_ * HW + hw;
    int c0 = threadIdx.x, c1 = c0 + 256, c2 = c0 + 512;
    float v0 = xp[(size_t)c0 * HW];
    float v1 = xp[(size_t)c1 * HW];
    float v2 = xp[(size_t)c2 * HW];
    float s  = v0 + v1 + v2;
    float sq = v0 * v0 + v1 * v1 + v2 * v2;
    __shared__ float rs[8], rq[8];
#pragma unroll
    for (int o = 16; o; o >>= 1) {
        s  += __shfl_xor_sync(~0u, s, o);
        sq += __shfl_xor_sync(~0u, sq, o);
    }
    int wid = threadIdx.x >> 5, lid = threadIdx.x & 31;
    if (lid == 0) { rs[wid] = s; rq[wid] = sq; }
    __syncthreads();
    if (threadIdx.x == 0) {
        float ts = 0.f, tq = 0.f;
        for (int i = 0; i < 8; i++) { ts += rs[i]; tq += rq[i]; }
        rs[0] = ts; rq[0] = tq;
    }
    __syncthreads();
    float mean = rs[0] * (1.f / DIM_);
    float var  = rq[0] * (1.f / DIM_) - mean * mean;
    float inv  = rsqrtf(var + EPS_);
    const float* md = g_mod + t * (2 * DIM_);
    __half* hP = (__half*)g_hP;
#pragma unroll
    for (int r = 0; r < 3; r++) {
        int c = c0 + r * 256;
        float v = (r == 0) ? v0 : (r == 1) ? v1 : v2;
        float y = (v - mean) * inv * (1.f + md[c]) + md[DIM_ + c];
        hP[aposW(n, c, KB16H) * 2 + (c & 1)] = __float2half_rn(y);
    }
}

// ---------------- GEMM 1: fused = h @ W_fused + b_fused (fp16) ----------------
// CTA 128x128, 8 warps (4m x 2n), k-chunk 32 (2 k16 atoms), 2-stage cp.async.
__global__ void __launch_bounds__(256, 2) k_gemm1_mma(const float* __restrict__ bf) {
    extern __shared__ uint4 smU[];   // [2][A 512 u4 | B 512 u4]
    const int tid = threadIdx.x, wid = tid >> 5, lane = tid & 31;
    const int wm = wid & 3, wn = wid >> 2;
    const int g = lane >> 2, tig = lane & 3;
    const int bm = blockIdx.y * 128, BN = blockIdx.x * 128;
    const int mblk0 = bm >> 4, nblk0 = BN >> 4;

    float acc[2][8][4];
#pragma unroll
    for (int a = 0; a < 2; a++)
#pragma unroll
        for (int b = 0; b < 8; b++)
#pragma unroll
            for (int c = 0; c < 4; c++) acc[a][b][c] = 0.f;

    load_plane(smU,       g_hP, mblk0, KB16H, 0, tid);
    load_plane(smU + 512, g_w1, nblk0, KB16H, 0, tid);
    CP_COMMIT(); CP_WAIT0();
    __syncthreads();

    const int NIT = KB16H / 2;   // 24
    for (int kt = 0; kt < NIT; kt++) {
        int cur = kt & 1, nxt = cur ^ 1;
        if (kt + 1 < NIT) {
            int kat = (kt + 1) * 2;
            load_plane(smU + nxt * 1024,       g_hP, mblk0, KB16H, kat, tid);
            load_plane(smU + nxt * 1024 + 512, g_w1, nblk0, KB16H, kat, tid);
            CP_COMMIT();
        }
        const uint4* Ab = smU + cur * 1024;
        const uint4* Bb = Ab + 512;
#pragma unroll
        for (int ks = 0; ks < 2; ks++) {
            uint4 a0 = Ab[((wm * 2 + 0) * 2 + ks) * 32 + lane];
            uint4 a1 = Ab[((wm * 2 + 1) * 2 + ks) * 32 + lane];
#pragma unroll
            for (int nbp = 0; nbp < 4; nbp++) {
                uint4 b = Bb[((wn * 4 + nbp) * 2 + ks) * 32 + lane];
                mmah(acc[0][nbp * 2 + 0], a0, b.x, b.y);
                mmah(acc[0][nbp * 2 + 1], a0, b.z, b.w);
                mmah(acc[1][nbp * 2 + 0], a1, b.x, b.y);
                mmah(acc[1][nbp * 2 + 1], a1, b.z, b.w);
            }
        }
        if (kt + 1 < NIT) CP_WAIT0();
        __syncthreads();
    }

    const bool qkv_tile = (BN < QKV_N);
#pragma unroll
    for (int mb = 0; mb < 2; mb++) {
#pragma unroll
        for (int rr = 0; rr < 2; rr++) {
            int row = bm + wm * 32 + mb * 16 + rr * 8 + g;
            if (row >= NTOK) continue;
#pragma unroll
            for (int nb = 0; nb < 8; nb++) {
                int col = BN + wn * 64 + nb * 8 + 2 * tig;
                float vx = acc[mb][nb][rr * 2 + 0] + bf[col];
                float vy = acc[mb][nb][rr * 2 + 1] + bf[col + 1];
                if (qkv_tile) {
                    *(float2*)(g_qkv + (size_t)row * QKV_N + col) = make_float2(vx, vy);
                } else {
                    g_aP[aposW(row, col - 1536, KB16A)] =
                        pack_h2(silu_f(vx), silu_f(vy));
                }
            }
        }
    }
}

// ---------------- GEMM 2: [xa | silu(mlp)] @ [Wo;Wm], split-K=6 (fp16) --------
__global__ void __launch_bounds__(256, 2) k_gemm2_mma() {
    extern __shared__ uint4 smU[];
    const int tid = threadIdx.x, wid = tid >> 5, lane = tid & 31;
    const int wm = wid & 3, wn = wid >> 2;
    const int g = lane >> 2, tig = lane & 3;
    const int bm = blockIdx.y * 128, BN = blockIdx.x * 128;
    const int z = blockIdx.z;
    const int mblk0 = bm >> 4, nblk0 = BN >> 4;
    const int kat0 = z * (KSPLIT2 / 16);    // 40 per split

    float acc[2][8][4];
#pragma unroll
    for (int a = 0; a < 2; a++)
#pragma unroll
        for (int b = 0; b < 8; b++)
#pragma unroll
            for (int c = 0; c < 4; c++) acc[a][b][c] = 0.f;

    load_plane(smU,       g_aP, mblk0, KB16A, kat0, tid);
    load_plane(smU + 512, g_w2, nblk0, KB16A, kat0, tid);
    CP_COMMIT(); CP_WAIT0();
    __syncthreads();

    const int NIT = KSPLIT2 / 32;   // 20
    for (int kt = 0; kt < NIT; kt++) {
        int cur = kt & 1, nxt = cur ^ 1;
        if (kt + 1 < NIT) {
            int kat = kat0 + (kt + 1) * 2;
            load_plane(smU + nxt * 1024,       g_aP, mblk0, KB16A, kat, tid);
            load_plane(smU + nxt * 1024 + 512, g_w2, nblk0, KB16A, kat, tid);
            CP_COMMIT();
        }
        const uint4* Ab = smU + cur * 1024;
        const uint4* Bb = Ab + 512;
#pragma unroll
        for (int ks = 0; ks < 2; ks++) {
            uint4 a0 = Ab[((wm * 2 + 0) * 2 + ks) * 32 + lane];
            uint4 a1 = Ab[((wm * 2 + 1) * 2 + ks) * 32 + lane];
#pragma unroll
            for (int nbp = 0; nbp < 4; nbp++) {
                uint4 b = Bb[((wn * 4 + nbp) * 2 + ks) * 32 + lane];
                mmah(acc[0][nbp * 2 + 0], a0, b.x, b.y);
                mmah(acc[0][nbp * 2 + 1], a0, b.z, b.w);
                mmah(acc[1][nbp * 2 + 0], a1, b.x, b.y);
                mmah(acc[1][nbp * 2 + 1], a1, b.z, b.w);
            }
        }
        if (kt + 1 < NIT) CP_WAIT0();
        __syncthreads();
    }

#pragma unroll
    for (int mb = 0; mb < 2; mb++) {
#pragma unroll
        for (int rr = 0; rr < 2; rr++) {
            int row = bm + wm * 32 + mb * 16 + rr * 8 + g;
            if (row >= NTOK) continue;
            float* dst = g_part + ((size_t)z * NTOK + row) * DIM_ + BN + wn * 64;
#pragma unroll
            for (int nb = 0; nb < 8; nb++) {
                int col = nb * 8 + 2 * tig;
                *(float2*)(dst + col) =
                    make_float2(acc[mb][nb][rr * 2 + 0], acc[mb][nb][rr * 2 + 1]);
            }
        }
    }
}

// ---------------- kernel 4: qk-norm + RoPE + scatter q/k/v --------------------
__global__ void __launch_bounds__(512) k_qkv(const float* __restrict__ qn_w,
                                             const float* __restrict__ qn_b,
                                             const float* __restrict__ kn_w,
                                             const float* __restrict__ kn_b) {
    int n = blockIdx.x;
    int head = threadIdx.x >> 5;
    int lane = threadIdx.x & 31;
    int t = n / HW, hh = (n % HW) / RESO, ww = n % RESO;
    const float* fp = g_qkv + (size_t)n * QKV_N + head * DH_;
    float2 q2 = make_float2(0.f, 0.f), k2 = q2, v2 = q2;
    if (lane < 24) {
        q2 = *(const float2*)(fp + 2 * lane);
        k2 = *(const float2*)(fp + DIM_ + 2 * lane);
        v2 = *(const float2*)(fp + 2 * DIM_ + 2 * lane);
    }
    float qs = q2.x + q2.y, qq = q2.x * q2.x + q2.y * q2.y;
    float ks = k2.x + k2.y, kq = k2.x * k2.x + k2.y * k2.y;
#pragma unroll
    for (int o = 16; o; o >>= 1) {
        qs += __shfl_xor_sync(~0u, qs, o);
        qq += __shfl_xor_sync(~0u, qq, o);
        ks += __shfl_xor_sync(~0u, ks, o);
        kq += __shfl_xor_sync(~0u, kq, o);
    }
    if (lane < 24) {
        float qm = qs * (1.f / DH_), qv = qq * (1.f / DH_) - qm * qm;
        float km = ks * (1.f / DH_), kv = kq * (1.f / DH_) - km * km;
        float qi = rsqrtf(qv + EPS_), ki = rsqrtf(kv + EPS_);
        int j0 = 2 * lane, j1 = j0 + 1;
        float qn0 = (q2.x - qm) * qi * qn_w[j0] + qn_b[j0];
        float qn1 = (q2.y - qm) * qi * qn_w[j1] + qn_b[j1];
        float kn0 = (k2.x - km) * ki * kn_w[j0] + kn_b[j0];
        float kn1 = (k2.y - km) * ki * kn_w[j1] + kn_b[j1];
        int i = lane;
        int idx;  float pos;
        if (i < 8)       { idx = i;      pos = (float)t;  }
        else if (i < 16) { idx = i - 8;  pos = (float)hh; }
        else             { idx = i - 16; pos = (float)ww; }
        float ang = pos * powf(10000.f, -(float)idx * 0.125f);
        float c = cosf(ang), sn = sinf(ang);
        const float qsc = 0.14433756729740643f;  // 48^-0.5
        size_t base = ((size_t)head * NTOK + n) * DH_;
        *(float2*)(g_q + base + j0) =
            make_float2((qn0 * c - qn1 * sn) * qsc, (qn0 * sn + qn1 * c) * qsc);
        *(float2*)(g_k + base + j0) =
            make_float2(kn0 * c - kn1 * sn, kn0 * sn + kn1 * c);
        *(float2*)(g_v + base + j0) = v2;
    }
}

// ---------------- kernel 5: neighborhood attention (75 nbrs) ------------------
__global__ void __launch_bounds__(512) k_attn() {
    __shared__ float sq[HEADS_][DH_];
    int n = blockIdx.x;
    int head = threadIdx.x >> 5, lane = threadIdx.x & 31;
    int hh = (n % HW) / RESO, ww = n % RESO;
    size_t hb = (size_t)head * NTOK * DH_;
    if (lane < 24)
        *(float2*)&sq[head][2 * lane] = *(const float2*)(g_q + hb + (size_t)n * DH_ + 2 * lane);
    __syncwarp();
    int ih0 = min(max(hh - 2, 0), RESO - 5);
    int iw0 = min(max(ww - 2, 0), RESO - 5);
    float logit[3]; int nn[3];
#pragma unroll
    for (int s = 0; s < 3; s++) {
        int a = s * 32 + lane;
        logit[s] = -1e30f; nn[s] = 0;
        if (a < 75) {
            int at = a / 25, r = a % 25, ah = r / 5, aw = r % 5;
            int np = at * HW + (ih0 + ah) * RESO + (iw0 + aw);
            nn[s] = np;
            const float* kp = g_k + hb + (size_t)np * DH_;
            float d = 0.f;
#pragma unroll
            for (int j4 = 0; j4 < 12; j4++) {
                float4 kvv = *(const float4*)(kp + j4 * 4);
                d += kvv.x * sq[head][j4 * 4 + 0] + kvv.y * sq[head][j4 * 4 + 1]
                   + kvv.z * sq[head][j4 * 4 + 2] + kvv.w * sq[head][j4 * 4 + 3];
            }
            logit[s] = d;
        }
    }
    float m = fmaxf(fmaxf(logit[0], logit[1]), logit[2]);
#pragma unroll
    for (int o = 16; o; o >>= 1) m = fmaxf(m, __shfl_xor_sync(~0u, m, o));
    float p[3];
    p[0] = expf(logit[0] - m);
    p[1] = expf(logit[1] - m);
    p[2] = expf(logit[2] - m);
    float ssum = p[0] + p[1] + p[2];
#pragma unroll
    for (int o = 16; o; o >>= 1) ssum += __shfl_xor_sync(~0u, ssum, o);
    float inv = 1.f / ssum;
    float o0 = 0.f, o1 = 0.f;
#pragma unroll
    for (int s = 0; s < 3; s++) {
        int lim = (s == 2) ? 11 : 32;
        for (int src = 0; src < lim; src++) {
            float pa = __shfl_sync(~0u, p[s], src);
            int  np = __shfl_sync(~0u, nn[s], src);
            const float* vp = g_v + hb + (size_t)np * DH_;
            o0 += pa * vp[lane];
            if (lane < 16) o1 += pa * vp[lane + 32];
        }
    }
    // write xa into gemm2 A plane (k index = channel)
    int ch = head * DH_;
    __half* aP = (__half*)g_aP;
    {
        int k = ch + lane;
        aP[aposW(n, k, KB16A) * 2 + (k & 1)] = __float2half_rn(o0 * inv);
    }
    if (lane < 16) {
        int k = ch + 32 + lane;
        aP[aposW(n, k, KB16A) * 2 + (k & 1)] = __float2half_rn(o1 * inv);
    }
}

// ---------------- kernel 7: reduce partials + skip + bias + transpose ---------
__global__ void __launch_bounds__(256) k_fin(const float* __restrict__ x,
                                             const float* __restrict__ bm_,
                                             float* __restrict__ out) {
    __shared__ float s[32][33];
    int hw0 = blockIdx.x * 32, c0 = blockIdx.y * 32, t = blockIdx.z;
    int lx = threadIdx.x & 31, lyb = threadIdx.x >> 5;
#pragma unroll
    for (int r = 0; r < 4; r++) {
        int hwl = lyb + r * 8;
        int c = c0 + lx;
        size_t nidx = ((size_t)(t * HW + hw0 + hwl)) * DIM_ + c;
        float sum = bm_[c];
#pragma unroll
        for (int z = 0; z < NSPLIT; z++)
            sum += g_part[(size_t)z * NTOK * DIM_ + nidx];
        s[hwl][lx] = sum;
    }
    __syncthreads();
#pragma unroll
    for (int r = 0; r < 4; r++) {
        int cl = lyb + r * 8;
        size_t oi = ((size_t)(t * DIM_ + c0 + cl)) * HW + hw0 + lx;
        out[oi] = x[oi] + s[lx][cl];
    }
}

// ---------------------------------- launcher ----------------------------------
extern "C" void kernel_launch(void* const* d_in, const int* in_sizes, int n_in,
                              void* d_out, int out_size) {
    const float* x       = (const float*)d_in[0];
    const float* emb     = (const float*)d_in[1];
    const float* w_mod   = (const float*)d_in[2];
    const float* b_mod   = (const float*)d_in[3];
    const float* qn_w    = (const float*)d_in[4];
    const float* qn_b    = (const float*)d_in[5];
    const float* kn_w    = (const float*)d_in[6];
    const float* kn_b    = (const float*)d_in[7];
    const float* W_fused = (const float*)d_in[8];
    const float* b_fused = (const float*)d_in[9];
    const float* W_out   = (const float*)d_in[10];
    const float* W_mlp   = (const float*)d_in[11];
    const float* b_mlp   = (const float*)d_in[12];
    float* out = (float*)d_out;

    static int attr_done = 0;
    if (!attr_done) {
        cudaFuncSetAttribute(k_gemm1_mma, cudaFuncAttributeMaxDynamicSharedMemorySize, SMEM_BYTES);
        cudaFuncSetAttribute(k_gemm2_mma, cudaFuncAttributeMaxDynamicSharedMemorySize, SMEM_BYTES);
        attr_done = 1;
    }

    unsigned *w1, *w2;
    cudaGetSymbolAddress((void**)&w1, g_w1);
    cudaGetSymbolAddress((void**)&w2, g_w2);

    k_mod<<<dim3(6, 3), 256>>>(emb, w_mod, b_mod);
    k_ln<<<NTOK, 256>>>(x);
    k_tr<<<dim3(FUSED_N / 32, DIM_ / 32), 256>>>(W_fused, w1, FUSED_N, KB16H, 0);
    k_tr<<<dim3(DIM_ / 32, DIM_ / 32), 256>>>(W_out, w2, DIM_, KB16A, 0);
    k_tr<<<dim3(DIM_ / 32, MLP_ / 32), 256>>>(W_mlp, w2, DIM_, KB16A, DIM_);

    k_gemm1_mma<<<dim3(FUSED_N / 128, 14), 256, SMEM_BYTES>>>(b_fused);
    k_qkv<<<NTOK, 512>>>(qn_w, qn_b, kn_w, kn_b);
    k_attn<<<NTOK, 512>>>();
    k_gemm2_mma<<<dim3(DIM_ / 128, 14, NSPLIT), 256, SMEM_BYTES>>>();
    k_fin<<<dim3(RESO * RESO / 32, DIM_ / 32, T_), 256>>>(x, b_mlp, out);
}